// round 6
// baseline (speedup 1.0000x reference)
#include <cuda_runtime.h>

// CenterLoss: loss = (1/B) * sum_i [ sxx/m^2 + scc - 2*sxc/m ],  m = max(sqrt(sxx),1e-12)
// B=16384, C=8192, D=64.
// R5 (resubmit after infra failure): shortest-chain version with SAFE dtype handling.
//  - labels are speculatively read as int32 (in-bounds for both int32 and int64 buffers)
//  - per-warp dtype probe: one LDG from bytes [4..255] of labels (in-bounds always),
//    __ballot on nonzero "odd words" -> int32 iff any nonzero (P_fail ~ 8192^-32)
//  - no __syncthreads, no shared memory
//  - per-warp atomicAdd + warp-granular count finalize

#define EPS 1e-12f
#define R 2   // rows per half-warp

__device__ float g_acc;            // zero at load; reset by finalizer each run
__device__ unsigned int g_count;

__global__ void __launch_bounds__(256)
center_loss_kernel(const float4* __restrict__ x,
                   const void* __restrict__ labels,
                   const float4* __restrict__ centers,
                   float* __restrict__ out,
                   float inv_batch, unsigned int total_warps)
{
    const int lane = threadIdx.x & 31;
    const int wid  = threadIdx.x >> 5;
    const int hw   = lane >> 4;         // half-warp id
    const int sub  = lane & 15;         // lane within half-warp
    const int base = (((blockIdx.x * 8 + wid) * 2) + hw) * R;

    // ---- independent front-batched loads: probe, labels(int32 view), x ----
    // Probe reads 32-bit words at indices 1,3,...,63 (bytes 4..255): in-bounds
    // for any labels dtype. If labels are int64 (little-endian) these are the
    // high words of slots 0..31, all zero for values in [0,8192). If labels are
    // int32 these are labels[1..63:2], random -> essentially never all zero.
    unsigned int probe = ((const unsigned int*)labels)[2 * lane + 1];

    int lab[R];
    #pragma unroll
    for (int i = 0; i < R; ++i)
        lab[i] = ((const int*)labels)[base + i];   // speculative int32 view

    float4 xv[R];
    #pragma unroll
    for (int i = 0; i < R; ++i)
        xv[i] = x[(base + i) * 16 + sub];

    bool is32 = __ballot_sync(0xffffffffu, probe != 0u) != 0u;
    if (!is32) {  // int64 labels: reload (never taken for this dataset)
        #pragma unroll
        for (int i = 0; i < R; ++i)
            lab[i] = (int)((const long long*)labels)[base + i];
    }

    float4 cv[R];
    #pragma unroll
    for (int i = 0; i < R; ++i)
        cv[i] = centers[lab[i] * 16 + sub];

    // ---- per-row sums + half-warp (16-lane) reduction ----
    float local = 0.0f;
    #pragma unroll
    for (int i = 0; i < R; ++i) {
        float sxx = xv[i].x*xv[i].x + xv[i].y*xv[i].y + xv[i].z*xv[i].z + xv[i].w*xv[i].w;
        float sxc = xv[i].x*cv[i].x + xv[i].y*cv[i].y + xv[i].z*cv[i].z + xv[i].w*cv[i].w;
        float scc = cv[i].x*cv[i].x + cv[i].y*cv[i].y + cv[i].z*cv[i].z + cv[i].w*cv[i].w;
        #pragma unroll
        for (int o = 8; o; o >>= 1) {
            sxx += __shfl_xor_sync(0xffffffffu, sxx, o);
            sxc += __shfl_xor_sync(0xffffffffu, sxc, o);
            scc += __shfl_xor_sync(0xffffffffu, scc, o);
        }
        if (sub == 0) {
            float m = fmaxf(sqrtf(sxx), EPS);
            float r = 1.0f / m;
            local += sxx * r * r + scc - 2.0f * sxc * r;
        }
    }
    // fold the two half-warps into lane 0
    local += __shfl_xor_sync(0xffffffffu, local, 16);

    // ---- per-warp atomic + warp-granular finalize ----
    if (lane == 0) {
        atomicAdd(&g_acc, local);
        __threadfence();
        unsigned int old = atomicAdd(&g_count, 1u);
        if (old == total_warps - 1u) {
            float total = atomicExch(&g_acc, 0.0f);
            *out = total * inv_batch;
            g_count = 0u;
        }
    }
}

extern "C" void kernel_launch(void* const* d_in, const int* in_sizes, int n_in,
                              void* d_out, int out_size)
{
    const float4* x       = (const float4*)d_in[0];
    const void*   labels  = d_in[1];
    const float4* centers = (const float4*)d_in[2];
    float*        out     = (float*)d_out;

    const int batch = in_sizes[0] / 64;              // 16384
    const int rows_per_block = 8 * 2 * R;            // 32
    const int blocks = batch / rows_per_block;       // 512
    center_loss_kernel<<<blocks, 256>>>(x, labels, centers, out,
                                        1.0f / (float)batch,
                                        (unsigned int)(blocks * 8));
}

// round 7
// speedup vs baseline: 1.6866x; 1.6866x over previous
#include <cuda_runtime.h>

// CenterLoss: loss = (1/B) * sum_i [ sxx/m^2 + scc - 2*sxc/m ],  m = max(sqrt(sxx),1e-12)
// B=16384, C=8192, D=64.
// R6 = R3's memory/atomic structure + R5's off-critical-path dtype probe.
//  - probe load (bytes 4..255 of labels, always in-bounds) runs concurrently with
//    label/x loads; __ballot decides int32 vs int64 (P_fail ~ 8192^-32)
//  - speculative int32 label view (in-bounds for both dtypes)
//  - half-warp x float4 per row, R=2 rows per half-warp, 256 threads/block
//  - block-level smem reduce -> exactly 512 fp32 atomics + 512 counter atomics

#define EPS 1e-12f
#define R 2   // rows per half-warp

__device__ float g_acc;            // zero at load; reset by finalizer each run
__device__ unsigned int g_count;

__global__ void __launch_bounds__(256)
center_loss_kernel(const float4* __restrict__ x,
                   const void* __restrict__ labels,
                   const float4* __restrict__ centers,
                   float* __restrict__ out,
                   float inv_batch)
{
    __shared__ float ssum[8];

    const int tid  = threadIdx.x;
    const int lane = tid & 31;
    const int wid  = tid >> 5;
    const int hw   = lane >> 4;         // half-warp id
    const int sub  = lane & 15;         // lane within half-warp
    const int base = (((blockIdx.x * 8 + wid) * 2) + hw) * R;  // first of R rows

    // ---- independent front-batched loads: probe, labels, x ----
    // Probe: 32-bit words at indices 1,3,...,63 (bytes 4..255) — in-bounds for
    // any dtype. int64 labels in [0,8192): all zero. int32: essentially never.
    unsigned int probe = ((const unsigned int*)labels)[2 * lane + 1];

    // Speculative int32 view; R=2 consecutive labels as one int2 (LDG.64).
    int2 lpair = ((const int2*)labels)[base >> 1];

    float4 xv[R];
    #pragma unroll
    for (int i = 0; i < R; ++i)
        xv[i] = x[(base + i) * 16 + sub];

    bool is32 = __ballot_sync(0xffffffffu, probe != 0u) != 0u;
    int lab[R];
    lab[0] = lpair.x; lab[1] = lpair.y;
    if (!is32) {  // int64 labels: reload (not taken for this dataset)
        #pragma unroll
        for (int i = 0; i < R; ++i)
            lab[i] = (int)((const long long*)labels)[base + i];
    }

    float4 cv[R];
    #pragma unroll
    for (int i = 0; i < R; ++i)
        cv[i] = centers[lab[i] * 16 + sub];

    // ---- per-row sums + half-warp (16-lane) reduction ----
    float local = 0.0f;
    #pragma unroll
    for (int i = 0; i < R; ++i) {
        float sxx = xv[i].x*xv[i].x + xv[i].y*xv[i].y + xv[i].z*xv[i].z + xv[i].w*xv[i].w;
        float sxc = xv[i].x*cv[i].x + xv[i].y*cv[i].y + xv[i].z*cv[i].z + xv[i].w*cv[i].w;
        float scc = cv[i].x*cv[i].x + cv[i].y*cv[i].y + cv[i].z*cv[i].z + cv[i].w*cv[i].w;
        #pragma unroll
        for (int o = 8; o; o >>= 1) {
            sxx += __shfl_xor_sync(0xffffffffu, sxx, o);
            sxc += __shfl_xor_sync(0xffffffffu, sxc, o);
            scc += __shfl_xor_sync(0xffffffffu, scc, o);
        }
        if (sub == 0) {
            float m = fmaxf(sqrtf(sxx), EPS);
            float r = 1.0f / m;
            local += sxx * r * r + scc - 2.0f * sxc * r;
        }
    }
    // fold the two half-warps into lane 0 of each warp
    local += __shfl_xor_sync(0xffffffffu, local, 16);

    // ---- block reduce: 8 warp partials -> 1 atomic per block ----
    if (lane == 0) ssum[wid] = local;
    __syncthreads();
    if (tid == 0) {
        float s = 0.0f;
        #pragma unroll
        for (int i = 0; i < 8; ++i) s += ssum[i];
        atomicAdd(&g_acc, s);
        __threadfence();
        unsigned int old = atomicAdd(&g_count, 1u);
        if (old == gridDim.x - 1u) {
            float total = atomicExch(&g_acc, 0.0f);
            *out = total * inv_batch;
            g_count = 0u;
        }
    }
}

extern "C" void kernel_launch(void* const* d_in, const int* in_sizes, int n_in,
                              void* d_out, int out_size)
{
    const float4* x       = (const float4*)d_in[0];
    const void*   labels  = d_in[1];
    const float4* centers = (const float4*)d_in[2];
    float*        out     = (float*)d_out;

    const int batch = in_sizes[0] / 64;              // 16384
    const int rows_per_block = 8 * 2 * R;            // 32
    const int blocks = batch / rows_per_block;       // 512
    center_loss_kernel<<<blocks, 256>>>(x, labels, centers, out,
                                        1.0f / (float)batch);
}

// round 8
// speedup vs baseline: 1.7588x; 1.0428x over previous
#include <cuda_runtime.h>

// CenterLoss: loss = (1/B) * sum_i [ sxx/m^2 + scc - 2*sxc/m ],  m = max(sqrt(sxx),1e-12)
// B=16384, C=8192, D=64.
// R8 = R6 with the dtype ballot taken OFF the center-gather critical path.
// Key safety fact: interpreting an int64 label buffer (values in [0,8192)) as
// int32 yields alternating {label, 0} — every value is a valid centers row.
// So the int32-speculative gather is in-bounds for EITHER dtype, and the
// ballot only gates the (never-taken) int64 correction reload.
//
// Critical path: label LDG -> center LDG -> 4 shuffle rounds -> block reduce
// -> 1 atomic/block. Probe + ballot overlap the gather.

#define EPS 1e-12f
#define R 2   // rows per half-warp

__device__ float g_acc;            // zero at load; reset by finalizer each run
__device__ unsigned int g_count;

__global__ void __launch_bounds__(256)
center_loss_kernel(const float4* __restrict__ x,
                   const void* __restrict__ labels,
                   const float4* __restrict__ centers,
                   float* __restrict__ out,
                   float inv_batch)
{
    __shared__ float ssum[8];

    const int tid  = threadIdx.x;
    const int lane = tid & 31;
    const int wid  = tid >> 5;
    const int hw   = lane >> 4;         // half-warp id
    const int sub  = lane & 15;         // lane within half-warp
    const int base = (((blockIdx.x * 8 + wid) * 2) + hw) * R;  // first of R rows

    // ---- chain head: labels first (int32 view, safe for either dtype) ----
    int2 lpair = ((const int2*)labels)[base >> 1];

    // probe (bytes 4..255, in-bounds for any dtype) — resolved later, off-chain
    unsigned int probe = ((const unsigned int*)labels)[2 * lane + 1];

    // independent x loads fill the label-load shadow
    float4 xv[R];
    #pragma unroll
    for (int i = 0; i < R; ++i)
        xv[i] = x[(base + i) * 16 + sub];

    // ---- speculative gather straight off lpair (no ballot in the chain) ----
    int lab[R];
    lab[0] = lpair.x; lab[1] = lpair.y;
    float4 cv[R];
    #pragma unroll
    for (int i = 0; i < R; ++i)
        cv[i] = centers[lab[i] * 16 + sub];

    // dtype resolution overlaps the gather; int64 labels => all probes zero
    bool is32 = __ballot_sync(0xffffffffu, probe != 0u) != 0u;
    if (!is32) {  // int64 correction path (never taken for this dataset)
        #pragma unroll
        for (int i = 0; i < R; ++i) {
            lab[i] = (int)((const long long*)labels)[base + i];
            cv[i]  = centers[lab[i] * 16 + sub];
        }
    }

    // ---- per-row sums + half-warp (16-lane) reduction ----
    float local = 0.0f;
    #pragma unroll
    for (int i = 0; i < R; ++i) {
        float sxx = xv[i].x*xv[i].x + xv[i].y*xv[i].y + xv[i].z*xv[i].z + xv[i].w*xv[i].w;
        float sxc = xv[i].x*cv[i].x + xv[i].y*cv[i].y + xv[i].z*cv[i].z + xv[i].w*cv[i].w;
        float scc = cv[i].x*cv[i].x + cv[i].y*cv[i].y + cv[i].z*cv[i].z + cv[i].w*cv[i].w;
        #pragma unroll
        for (int o = 8; o; o >>= 1) {
            sxx += __shfl_xor_sync(0xffffffffu, sxx, o);
            sxc += __shfl_xor_sync(0xffffffffu, sxc, o);
            scc += __shfl_xor_sync(0xffffffffu, scc, o);
        }
        if (sub == 0) {
            float m = fmaxf(sqrtf(sxx), EPS);
            float r = 1.0f / m;
            local += sxx * r * r + scc - 2.0f * sxc * r;
        }
    }
    // fold the two half-warps into lane 0 of each warp
    local += __shfl_xor_sync(0xffffffffu, local, 16);

    // ---- block reduce: 8 warp partials -> 1 atomic per block ----
    if (lane == 0) ssum[wid] = local;
    __syncthreads();
    if (tid == 0) {
        float s = 0.0f;
        #pragma unroll
        for (int i = 0; i < 8; ++i) s += ssum[i];
        atomicAdd(&g_acc, s);
        __threadfence();
        unsigned int old = atomicAdd(&g_count, 1u);
        if (old == gridDim.x - 1u) {
            float total = atomicExch(&g_acc, 0.0f);
            *out = total * inv_batch;
            g_count = 0u;
        }
    }
}

extern "C" void kernel_launch(void* const* d_in, const int* in_sizes, int n_in,
                              void* d_out, int out_size)
{
    const float4* x       = (const float4*)d_in[0];
    const void*   labels  = d_in[1];
    const float4* centers = (const float4*)d_in[2];
    float*        out     = (float*)d_out;

    const int batch = in_sizes[0] / 64;              // 16384
    const int rows_per_block = 8 * 2 * R;            // 32
    const int blocks = batch / rows_per_block;       // 512
    center_loss_kernel<<<blocks, 256>>>(x, labels, centers, out,
                                        1.0f / (float)batch);
}